// round 12
// baseline (speedup 1.0000x reference)
#include <cuda_runtime.h>

#define Lg 2048
#define LMASK 2047
#define LSHIFT 11
#define NCELL (Lg * Lg)

#define R_OVER_5 0.5554f      /* 2.777 / 5 */
#define ETA 0.8f
#define ONE_MINUS_ETA 0.2f
#define GAMMA 0.8f
#define INV_K 2.0f            /* 1 / 0.5 */

// Tile geometry: 128 wide x 16 tall, 1024 threads, 2 consecutive cells/thread
#define TX 128
#define TY 16
// type staging: rows row0-3 .. row0+18 (22), cols col0-4 .. col0+131 (136 = 34 int4)
#define TROWS 22
#define TV4   34               /* int4 per staged row */
#define TSTR4 35               /* padded stride in int4 */
#define TSTR  140              /* padded stride in ints */
// upd: rows row0-1 .. row0+16 (18), cols col0-1 .. col0+128 (130) */
#define UROWS 18
#define UCOLS 130
#define USTR  132
#define NHALO 292              /* 18*130 - 16*128 ring cells */

__global__ __launch_bounds__(1024) void spgg_fused(
    const int* __restrict__ type_tm,
    const int* __restrict__ type_t,
    const float4* __restrict__ Q,
    const int* __restrict__ ldir,
    const float* __restrict__ lprob,
    float4* __restrict__ Q_out,
    float* __restrict__ type_out,
    float* __restrict__ profit_out)
{
    __shared__ int4  s_type4[TROWS * TSTR4];
    __shared__ float s_upd  [UROWS * USTR];
    const int* s_type = (const int*)s_type4;

    int tid  = threadIdx.x;
    int bx   = blockIdx.x & 15;    // 2048/128 = 16 column tiles
    int by   = blockIdx.x >> 4;    // 128 row tiles
    int row0 = by * TY;
    int col0 = bx * TX;

    int tr = tid >> 6;             // 0..15 (row within tile)
    int c0 = (tid & 63) << 1;      // 0,2,..,126 (first of 2 consecutive cols)
    int gbase = ((row0 + tr) << LSHIFT) | (col0 + c0);

    // ---- Stage type_t tile (+3 halo) as int4, wrap-indexed ----
    if (tid < TROWS * TV4) {       // 748 < 1024
        int r  = tid / TV4;
        int c4 = tid - r * TV4;
        int gr = (row0 - 3 + r) & LMASK;
        int gc = (col0 - 4 + (c4 << 2)) & LMASK;
        s_type4[r * TSTR4 + c4] = __ldg((const int4*)(type_t + (gr << LSHIFT) + gc));
    }

    // ---- Prefetch per-cell streams (loader == consumer, stays in regs) ----
    float4 qv0 = __ldcs(Q + gbase);
    float4 qv1 = __ldcs(Q + gbase + 1);
    int2   av  = __ldg ((const int2*)  (type_tm + gbase));
    int2   dv  = __ldcs((const int2*)  (ldir    + gbase));
    float2 pv  = __ldcs((const float2*)(lprob   + gbase));

    // ---- Prefetch halo-ring cell (threads 0..291) ----
    int hr = 0, hc = 0;
    float4 qh;
    int ah = 0;
    bool has_halo = (tid < NHALO);
    if (has_halo) {
        int h = tid;
        if (h < UCOLS)            { hr = 0;             hc = h;          }
        else if (h < 2 * UCOLS)   { hr = UROWS - 1;     hc = h - UCOLS;  }
        else { int s = h - 2 * UCOLS; hr = 1 + (s >> 1); hc = (s & 1) ? (UCOLS - 1) : 0; }
        int gr = (row0 - 1 + hr) & LMASK;
        int gc = (col0 - 1 + hc) & LMASK;
        int hg = (gr << LSHIFT) | gc;
        qh = __ldcs(Q + hg);
        ah = __ldg(type_tm + hg);
    }

    __syncthreads();

    // ---- Phase 2: profit (13-pt stencil from smem) + Q update ----
    float prf[2];
    {
        int AV[2] = {av.x, av.y};
        float4 qq[2] = {qv0, qv1};
        #pragma unroll
        for (int j = 0; j < 2; j++) {
            int cc = c0 + j;
            const int* st = s_type + (tr + 3) * TSTR + (cc + 4);
            int t00  = st[0];
            int orth = st[-1] + st[1] + st[-TSTR] + st[TSTR];
            int diag = st[-TSTR - 1] + st[-TSTR + 1] + st[TSTR - 1] + st[TSTR + 1];
            int far2 = st[-2] + st[2] + st[-2 * TSTR] + st[2 * TSTR];
            int S2   = 5 * t00 + 2 * (orth + diag) + far2;
            float profit = (float)S2 * R_OVER_5 - 5.0f * (float)t00;

            float4 q = qq[j];
            int A = AV[j], B = t00;
            float maxv = B ? fmaxf(q.z, q.w) : fmaxf(q.x, q.y);
            float old  = B ? (A ? q.w : q.y) : (A ? q.z : q.x);
            float upd  = ONE_MINUS_ETA * old + ETA * (profit + GAMMA * maxv);
            if (A == 0) { if (B == 0) q.x = upd; else q.y = upd; }
            else        { if (B == 0) q.z = upd; else q.w = upd; }

            s_upd[(tr + 1) * USTR + (cc + 1)] = upd;
            prf[j] = profit;
            __stcs(Q_out + gbase + j, q);
        }
    }
    __stcs((float2*)(profit_out + gbase), make_float2(prf[0], prf[1]));

    // halo cells: upd coords (hr, hc) -> type coords (hr+2, hc+3)
    if (has_halo) {
        const int* st = s_type + (hr + 2) * TSTR + (hc + 3);
        int t00  = st[0];
        int orth = st[-1] + st[1] + st[-TSTR] + st[TSTR];
        int diag = st[-TSTR - 1] + st[-TSTR + 1] + st[TSTR - 1] + st[TSTR + 1];
        int far2 = st[-2] + st[2] + st[-2 * TSTR] + st[2 * TSTR];
        int S2   = 5 * t00 + 2 * (orth + diag) + far2;
        float profit = (float)S2 * R_OVER_5 - 5.0f * (float)t00;

        float4 q = qh;
        int A = ah, B = t00;
        float maxv = B ? fmaxf(q.z, q.w) : fmaxf(q.x, q.y);
        float old  = B ? (A ? q.w : q.y) : (A ? q.z : q.x);
        s_upd[hr * USTR + hc] = ONE_MINUS_ETA * old + ETA * (profit + GAMMA * maxv);
    }
    __syncthreads();

    // ---- Phase 3: fermi from smem + register-resident dirs/probs ----
    {
        int DV[2] = {dv.x, dv.y};
        float PV[2] = {pv.x, pv.y};
        float ov[2];
        #pragma unroll
        for (int j = 0; j < 2; j++) {
            int cc = c0 + j;
            float u = s_upd[(tr + 1) * USTR + (cc + 1)];

            int d = DV[j];
            int ur, uc;
            if (d == 0)      { ur = tr + 1; uc = cc;     }   // col-1
            else if (d == 1) { ur = tr + 1; uc = cc + 2; }   // col+1
            else if (d == 2) { ur = tr;     uc = cc + 1; }   // row-1
            else             { ur = tr + 2; uc = cc + 1; }   // row+1

            float un = s_upd[ur * USTR + uc];
            int tmine = s_type[(tr + 3) * TSTR + (cc + 4)];
            int tn    = s_type[(ur + 2) * TSTR + (uc + 3)];

            float W = 1.0f / (1.0f + __expf((u - un) * INV_K));
            ov[j] = (float)((PV[j] <= W) ? tn : tmine);
        }
        __stcs((float2*)(type_out + gbase), make_float2(ov[0], ov[1]));
    }
}

// ---------------------------------------------------------------------------
// Launch: output layout = concat(Q_new[4N], type_t1[N], profit[N]) as float32
// ---------------------------------------------------------------------------
extern "C" void kernel_launch(void* const* d_in, const int* in_sizes, int n_in,
                              void* d_out, int out_size)
{
    const int*    type_tm = (const int*)   d_in[0];
    const int*    type_t  = (const int*)   d_in[1];
    const float4* Q       = (const float4*)d_in[2];
    const int*    ldir    = (const int*)   d_in[3];
    const float*  lprob   = (const float*) d_in[4];

    float* out        = (float*)d_out;
    float4* Q_out     = (float4*)out;                 // [0, 4N)
    float* type_out   = out + 4 * (size_t)NCELL;      // [4N, 5N)
    float* profit_out = out + 5 * (size_t)NCELL;      // [5N, 6N)

    const int blocks = (Lg / TX) * (Lg / TY);         // 16 * 128 = 2048

    spgg_fused<<<blocks, 1024>>>(type_tm, type_t, Q, ldir, lprob,
                                 Q_out, type_out, profit_out);
}

// round 13
// speedup vs baseline: 1.1622x; 1.1622x over previous
#include <cuda_runtime.h>

#define Lg 2048
#define LMASK 2047
#define LSHIFT 11
#define NCELL (Lg * Lg)

#define R_OVER_5 0.5554f      /* 2.777 / 5 */
#define ETA 0.8f
#define ONE_MINUS_ETA 0.2f
#define GAMMA 0.8f
#define INV_K 2.0f            /* 1 / 0.5 */

// 13-point fused (plus∘plus) stencil: center 5, orth-1 & diag 2, dist-2 1.
__device__ __forceinline__ float profit_at(const int* __restrict__ t,
                                           int row, int col, int* t00_out)
{
    int r0  = row << LSHIFT;
    int rm1 = ((row - 1) & LMASK) << LSHIFT;
    int rp1 = ((row + 1) & LMASK) << LSHIFT;
    int rm2 = ((row - 2) & LMASK) << LSHIFT;
    int rp2 = ((row + 2) & LMASK) << LSHIFT;
    int cm1 = (col - 1) & LMASK;
    int cp1 = (col + 1) & LMASK;
    int cm2 = (col - 2) & LMASK;
    int cp2 = (col + 2) & LMASK;

    int t00  = __ldg(t + r0 + col);
    int orth = __ldg(t + r0 + cm1) + __ldg(t + r0 + cp1)
             + __ldg(t + rm1 + col) + __ldg(t + rp1 + col);
    int diag = __ldg(t + rm1 + cm1) + __ldg(t + rm1 + cp1)
             + __ldg(t + rp1 + cm1) + __ldg(t + rp1 + cp1);
    int far2 = __ldg(t + r0 + cm2) + __ldg(t + r0 + cp2)
             + __ldg(t + rm2 + col) + __ldg(t + rp2 + col);

    int S2 = 5 * t00 + 2 * (orth + diag) + far2;
    *t00_out = t00;
    return (float)S2 * R_OVER_5 - 5.0f * (float)t00;
}

// Q-learning update value for a cell (identical FP sequence for self & neighbor
// recompute -> bitwise-identical upd values).
__device__ __forceinline__ float upd_val(float4 q, int A, int B, float profit)
{
    float maxv = B ? fmaxf(q.z, q.w) : fmaxf(q.x, q.y);
    float old  = B ? (A ? q.w : q.y) : (A ? q.z : q.x);
    return ONE_MINUS_ETA * old + ETA * (profit + GAMMA * maxv);
}

// ---------------------------------------------------------------------------
// Single sync-free kernel: profit + Q update + fermi, neighbor upd recomputed.
// ---------------------------------------------------------------------------
__global__ __launch_bounds__(256) void spgg_all(
    const int* __restrict__ type_tm,
    const int* __restrict__ type_t,
    const float4* __restrict__ Q,
    const int* __restrict__ ldir,
    const float* __restrict__ lprob,
    float4* __restrict__ Q_out,
    float* __restrict__ type_out,
    float* __restrict__ profit_out)
{
    int i = blockIdx.x * blockDim.x + threadIdx.x;
    int row = i >> LSHIFT;
    int col = i & LMASK;

    // ---- Front-batched independent loads for the self cell ----
    float4 qi = __ldg(Q + i);                 // default: L2 keeps it for neighbor re-read
    int    Ai = __ldg(type_tm + i);
    int    d  = __ldcs(ldir + i);
    float  p  = __ldcs(lprob + i);

    int t00;
    float profit = profit_at(type_t, row, col, &t00);

    // ---- Self Q update ----
    float upd = upd_val(qi, Ai, t00, profit);
    float4 qo = qi;
    if (Ai == 0) { if (t00 == 0) qo.x = upd; else qo.y = upd; }
    else         { if (t00 == 0) qo.z = upd; else qo.w = upd; }

    __stcs(Q_out + i, qo);
    __stcs(profit_out + i, profit);

    // ---- Neighbor index from learning direction ----
    int nrow = row, ncol = col;
    if (d == 0)      ncol = (col - 1) & LMASK;
    else if (d == 1) ncol = (col + 1) & LMASK;
    else if (d == 2) nrow = (row - 1) & LMASK;
    else             nrow = (row + 1) & LMASK;
    int ni = (nrow << LSHIFT) | ncol;

    // ---- Recompute neighbor's upd (identical FP sequence => identical value) ----
    float4 qn = __ldg(Q + ni);                // L2-resident (re-read within ~115KB of stream)
    int    An = __ldg(type_tm + ni);
    int t00n;
    float profit_n = profit_at(type_t, nrow, ncol, &t00n);
    float upd_n = upd_val(qn, An, t00n, profit_n);

    // ---- Fermi update ----
    float W = 1.0f / (1.0f + __expf((upd - upd_n) * INV_K));
    int out = (p <= W) ? t00n : t00;
    __stcs(type_out + i, (float)out);
}

// ---------------------------------------------------------------------------
// Launch: output layout = concat(Q_new[4N], type_t1[N], profit[N]) as float32
// ---------------------------------------------------------------------------
extern "C" void kernel_launch(void* const* d_in, const int* in_sizes, int n_in,
                              void* d_out, int out_size)
{
    const int*    type_tm = (const int*)   d_in[0];
    const int*    type_t  = (const int*)   d_in[1];
    const float4* Q       = (const float4*)d_in[2];
    const int*    ldir    = (const int*)   d_in[3];
    const float*  lprob   = (const float*) d_in[4];

    float* out        = (float*)d_out;
    float4* Q_out     = (float4*)out;                 // [0, 4N)
    float* type_out   = out + 4 * (size_t)NCELL;      // [4N, 5N)
    float* profit_out = out + 5 * (size_t)NCELL;      // [5N, 6N)

    spgg_all<<<NCELL / 256, 256>>>(type_tm, type_t, Q, ldir, lprob,
                                   Q_out, type_out, profit_out);
}

// round 14
// speedup vs baseline: 1.3013x; 1.1197x over previous
#include <cuda_runtime.h>

#define Lg 2048
#define LMASK 2047
#define LSHIFT 11
#define NCELL (Lg * Lg)

#define R_OVER_5 0.5554f      /* 2.777 / 5 */
#define ETA 0.8f
#define ONE_MINUS_ETA 0.2f
#define GAMMA 0.8f
#define INV_K 2.0f            /* 1 / 0.5 */

// Tile geometry: 64 wide x 32 tall, 512 threads, 4 inner cells/thread (col-major)
#define TX 64
#define TY 32
// type staging: rows row0-3 .. row0+34 (38), cols col0-4 .. col0+67 (72 = 18 int4)
#define TROWS 38
#define TV4   18               /* int4 per staged row */
#define TSTR4 19               /* padded stride in int4 */
#define TSTR  76               /* padded stride in ints */
// upd: rows row0-1 .. row0+32 (34), cols col0-1 .. col0+64 (66)
#define UROWS 34
#define UCOLS 66
#define USTR  68
#define NHALO 196              /* 34*66 - 32*64 ring cells */

__global__ __launch_bounds__(512) void spgg_fused(
    const int* __restrict__ type_tm,
    const int* __restrict__ type_t,
    const float4* __restrict__ Q,
    const int* __restrict__ ldir,
    const float* __restrict__ lprob,
    float4* __restrict__ Q_out,
    float* __restrict__ type_out,
    float* __restrict__ profit_out)
{
    __shared__ int4   s_type4[TROWS * TSTR4];
    __shared__ float  s_upd  [UROWS * USTR];
    __shared__ int4   s_dir4 [512];     // 32x64 dirs
    __shared__ float4 s_prob4[512];     // 32x64 probs
    const int*   s_type = (const int*)s_type4;
    const int*   s_dir  = (const int*)s_dir4;
    const float* s_prob = (const float*)s_prob4;

    int tid  = threadIdx.x;
    int bx   = blockIdx.x & 31;    // 2048/64 = 32 column tiles
    int by   = blockIdx.x >> 5;    // 64 row tiles
    int row0 = by * TY;
    int col0 = bx * TX;

    int tr0 = (tid >> 6) << 2;     // 0,4,..,28 (first of 4 rows)
    int tc  = tid & 63;

    // ---- Stage ldir/lprob to smem (coalesced int4/float4; regs die here) ----
    {
        int r  = tid >> 4;                  // 0..31
        int c4 = (tid & 15) << 2;           // 0,4,..,60
        int g  = ((row0 + r) << LSHIFT) | (col0 + c4);
        s_dir4 [tid] = __ldcs((const int4*)  (ldir  + g));
        s_prob4[tid] = __ldcs((const float4*)(lprob + g));
    }

    // ---- Issue type staging loads (int4, wrap-indexed; 684 total) ----
    int4 stage[2];
    int  sidx[2];
    #pragma unroll
    for (int k = 0; k < 2; k++) {
        int idx = tid + k * 512;
        if (idx < TROWS * TV4) {
            int r  = idx / TV4;
            int c4 = idx - r * TV4;
            int gr = (row0 - 3 + r) & LMASK;
            int gc = (col0 - 4 + (c4 << 2)) & LMASK;
            stage[k] = __ldg((const int4*)(type_t + (gr << LSHIFT) + gc));
            sidx[k]  = r * TSTR4 + c4;
        } else sidx[k] = -1;
    }

    // ---- Prefetch inner-cell Q/tm (4 cells per thread, col-major mapping) ----
    int gidx[4];
    float4 qv[4];
    int av[4];
    #pragma unroll
    for (int j = 0; j < 4; j++) {
        int tr = tr0 + j;
        gidx[j] = ((row0 + tr) << LSHIFT) | (col0 + tc);
        qv[j] = __ldcs(Q + gidx[j]);
        av[j] = __ldg(type_tm + gidx[j]);
    }

    // ---- Prefetch halo-ring cell (threads 0..195) ----
    int hr = 0, hc = 0;
    float4 qh;
    int ah = 0;
    bool has_halo = (tid < NHALO);
    if (has_halo) {
        int h = tid;
        if (h < UCOLS)            { hr = 0;             hc = h;          }
        else if (h < 2 * UCOLS)   { hr = UROWS - 1;     hc = h - UCOLS;  }
        else { int s = h - 2 * UCOLS; hr = 1 + (s >> 1); hc = (s & 1) ? (UCOLS - 1) : 0; }
        int gr = (row0 - 1 + hr) & LMASK;
        int gc = (col0 - 1 + hc) & LMASK;
        int hg = (gr << LSHIFT) | gc;
        qh = __ldcs(Q + hg);
        ah = __ldg(type_tm + hg);
    }

    // ---- Complete type staging, sync ----
    #pragma unroll
    for (int k = 0; k < 2; k++)
        if (sidx[k] >= 0) s_type4[sidx[k]] = stage[k];
    __syncthreads();

    // ---- Phase 2: profit (13-pt stencil from smem) + Q update ----
    #pragma unroll
    for (int j = 0; j < 4; j++) {
        int tr = tr0 + j;
        const int* st = s_type + (tr + 3) * TSTR + (tc + 4);
        int t00  = st[0];
        int orth = st[-1] + st[1] + st[-TSTR] + st[TSTR];
        int diag = st[-TSTR - 1] + st[-TSTR + 1] + st[TSTR - 1] + st[TSTR + 1];
        int far2 = st[-2] + st[2] + st[-2 * TSTR] + st[2 * TSTR];
        int S2   = 5 * t00 + 2 * (orth + diag) + far2;
        float profit = (float)S2 * R_OVER_5 - 5.0f * (float)t00;

        float4 q = qv[j];
        int A = av[j], B = t00;
        float maxv = B ? fmaxf(q.z, q.w) : fmaxf(q.x, q.y);
        float old  = B ? (A ? q.w : q.y) : (A ? q.z : q.x);
        float upd  = ONE_MINUS_ETA * old + ETA * (profit + GAMMA * maxv);
        if (A == 0) { if (B == 0) q.x = upd; else q.y = upd; }
        else        { if (B == 0) q.z = upd; else q.w = upd; }

        s_upd[(tr + 1) * USTR + (tc + 1)] = upd;
        __stcs(Q_out + gidx[j], q);
        __stcs(profit_out + gidx[j], profit);
    }

    // halo cells: upd coords (hr, hc) -> type coords (hr+2, hc+3)
    if (has_halo) {
        const int* st = s_type + (hr + 2) * TSTR + (hc + 3);
        int t00  = st[0];
        int orth = st[-1] + st[1] + st[-TSTR] + st[TSTR];
        int diag = st[-TSTR - 1] + st[-TSTR + 1] + st[TSTR - 1] + st[TSTR + 1];
        int far2 = st[-2] + st[2] + st[-2 * TSTR] + st[2 * TSTR];
        int S2   = 5 * t00 + 2 * (orth + diag) + far2;
        float profit = (float)S2 * R_OVER_5 - 5.0f * (float)t00;

        float4 q = qh;
        int A = ah, B = t00;
        float maxv = B ? fmaxf(q.z, q.w) : fmaxf(q.x, q.y);
        float old  = B ? (A ? q.w : q.y) : (A ? q.z : q.x);
        s_upd[hr * USTR + hc] = ONE_MINUS_ETA * old + ETA * (profit + GAMMA * maxv);
    }
    __syncthreads();

    // ---- Phase 3: fermi entirely from smem (zero global loads) ----
    #pragma unroll
    for (int j = 0; j < 4; j++) {
        int tr = tr0 + j;

        int   d = s_dir [tr * 64 + tc];
        float p = s_prob[tr * 64 + tc];

        float u = s_upd[(tr + 1) * USTR + (tc + 1)];

        int ur, uc;
        if (d == 0)      { ur = tr + 1; uc = tc;     }   // col-1
        else if (d == 1) { ur = tr + 1; uc = tc + 2; }   // col+1
        else if (d == 2) { ur = tr;     uc = tc + 1; }   // row-1
        else             { ur = tr + 2; uc = tc + 1; }   // row+1

        float un = s_upd[ur * USTR + uc];
        int tmine = s_type[(tr + 3) * TSTR + (tc + 4)];
        int tn    = s_type[(ur + 2) * TSTR + (uc + 3)];

        float W = 1.0f / (1.0f + __expf((u - un) * INV_K));
        int out = (p <= W) ? tn : tmine;
        __stcs(type_out + gidx[j], (float)out);
    }
}

// ---------------------------------------------------------------------------
// Launch: output layout = concat(Q_new[4N], type_t1[N], profit[N]) as float32
// ---------------------------------------------------------------------------
extern "C" void kernel_launch(void* const* d_in, const int* in_sizes, int n_in,
                              void* d_out, int out_size)
{
    const int*    type_tm = (const int*)   d_in[0];
    const int*    type_t  = (const int*)   d_in[1];
    const float4* Q       = (const float4*)d_in[2];
    const int*    ldir    = (const int*)   d_in[3];
    const float*  lprob   = (const float*) d_in[4];

    float* out        = (float*)d_out;
    float4* Q_out     = (float4*)out;                 // [0, 4N)
    float* type_out   = out + 4 * (size_t)NCELL;      // [4N, 5N)
    float* profit_out = out + 5 * (size_t)NCELL;      // [5N, 6N)

    const int blocks = (Lg / TX) * (Lg / TY);         // 32 * 64 = 2048

    spgg_fused<<<blocks, 512>>>(type_tm, type_t, Q, ldir, lprob,
                                Q_out, type_out, profit_out);
}